// round 10
// baseline (speedup 1.0000x reference)
#include <cuda_runtime.h>
#include <cstdint>

#define BS    128
#define NT    25
#define MQ    1024
#define CREC  107
#define CLOC  25
#define THREADS 384
#define NWARP (THREADS / 32)
#define TABN  4096            // intervals over [-8,8] -> h = 1/256
#define INFF  3.0e38f
#define PFREE 0x7fffffff

__device__ double   g_sums[BS * 2];
__device__ unsigned g_count;     // zero-init; reset by last block each launch

struct Smem {
  float  cost[NT][MQ];           // 100 KB
  float2 tab[TABN];              // 32 KB focal table (slope, base)
  unsigned long long rkey[NT];   // packed (f2ord(min)<<32)|argj per row
  float  u[NT + 1];
  int    p[MQ + 1];
  int    way[MQ + 1];
  int    tgt_cls[NT];
  int    match_q[NT];
  int    pend[NT];
  int    npend;
  int    is64;
  double warp_rec[NWARP];
  double warp_loc[NWARP];
  int    islast;
  double red_r[4], red_l[4];
};

// focal cost via 3 MUFU — used to build the table nodes (proven match-identical in R2/R7)
__device__ __forceinline__ float focal_mufu(float x) {
  float t = __expf(-x);
  float w = 1.0f + t;
  float L = __logf(w);
  float p = __fdividef(1.0f, w);
  return p * p * (0.25f * t * t * L - 0.75f * (x + L));
}

__device__ __forceinline__ float focal_tab(const float2* __restrict__ tab, float x) {
  float xi = fmaf(x, 256.0f, 2048.0f);
  xi = fminf(fmaxf(xi, 0.0f), 4095.99f);
  int   ii   = (int)xi;
  float frac = xi - (float)ii;
  float2 sb  = tab[ii];
  return fmaf(frac, sb.x, sb.y);
}

__device__ __forceinline__ float warp_max_f(float v) {
  #pragma unroll
  for (int o = 16; o; o >>= 1) v = fmaxf(v, __shfl_xor_sync(0xffffffffu, v, o));
  return v;
}
__device__ __forceinline__ float warp_sum_f(float v) {
  #pragma unroll
  for (int o = 16; o; o >>= 1) v += __shfl_xor_sync(0xffffffffu, v, o);
  return v;
}

// float -> order-preserving uint (all values finite here)
__device__ __forceinline__ unsigned f2ord(float v) {
  unsigned u = __float_as_uint(v);
  return (u & 0x80000000u) ? ~u : (u | 0x80000000u);
}
__device__ __forceinline__ float ord2f(unsigned s) {
  unsigned u = (s & 0x80000000u) ? (s & 0x7fffffffu) : ~s;
  return __uint_as_float(u);
}

__global__ __launch_bounds__(THREADS)
void rec_criterion_kernel(const float* __restrict__ rec,
                          const float* __restrict__ loc,
                          const int*   __restrict__ tgt32,
                          float* __restrict__ out) {
  extern __shared__ char smem_raw[];
  Smem& S = *reinterpret_cast<Smem*>(smem_raw);
  const int b   = blockIdx.x;
  const int tid = threadIdx.x;
  const int wid = tid >> 5, lane = tid & 31;

  // ---- detection + table build + init (one barrier) ----
  if (tid < 32) {
    int w = tgt32[2 * tid + 1];            // odd words of first 32 int64 slots
    unsigned bal = __ballot_sync(0xffffffffu, w != 0);
    if (tid == 0) S.is64 = (bal == 0u);
  }
  // build focal table in smem (slope, base per interval)
  for (int i = tid; i < TABN; i += THREADS) {
    const float h = 16.0f / TABN;
    float x0 = -8.0f + i * h;
    float f0 = focal_mufu(x0);
    float f1 = focal_mufu(x0 + h);
    S.tab[i] = make_float2(f1 - f0, f0);
  }
  for (int j = tid; j <= MQ; j += THREADS) S.p[j] = PFREE;
  if (tid < NT) S.rkey[tid] = 0xFFFFFFFFFFFFFFFFull;
  __syncthreads();

  if (tid < NT) {
    int t;
    if (S.is64) t = (int)(reinterpret_cast<const long long*>(tgt32)[b * NT + tid]);
    else        t = tgt32[b * NT + tid];
    S.tgt_cls[tid] = t;
  }
  __syncthreads();

  const float* recb = rec + (size_t)b * CREC * MQ;
  const float* locb = loc + (size_t)b * CLOC * MQ;

  // ---- Phase A: half-row items (50) over warps; table lookups; packed row-min ----
  for (int it = wid; it < 2 * NT; it += NWARP) {
    const int r = it >> 1, h = it & 1;
    const float4* rp = reinterpret_cast<const float4*>(recb + (size_t)S.tgt_cls[r] * MQ);
    const float4* lp = reinterpret_cast<const float4*>(locb + (size_t)r * MQ);
    float4* crow4 = reinterpret_cast<float4*>(&S.cost[r][0]);
    float m = INFF; int jb = 0;
    float4 rv[4], lv[4];
    #pragma unroll
    for (int k = 0; k < 4; k++) rv[k] = __ldg(rp + lane + ((h * 4 + k) << 5));
    #pragma unroll
    for (int k = 0; k < 4; k++) lv[k] = __ldg(lp + lane + ((h * 4 + k) << 5));
    #pragma unroll
    for (int k = 0; k < 4; k++) {
      int g = lane + ((h * 4 + k) << 5);       // float4 group; j = 4g..4g+3
      float4 c;
      c.x = fmaf(2.0f, focal_tab(S.tab, rv[k].x), focal_tab(S.tab, lv[k].x));
      c.y = fmaf(2.0f, focal_tab(S.tab, rv[k].y), focal_tab(S.tab, lv[k].y));
      c.z = fmaf(2.0f, focal_tab(S.tab, rv[k].z), focal_tab(S.tab, lv[k].z));
      c.w = fmaf(2.0f, focal_tab(S.tab, rv[k].w), focal_tab(S.tab, lv[k].w));
      crow4[g] = c;
      int j = g << 2;                           // ascending j per lane: first occurrence
      if (c.x < m) { m = c.x; jb = j; }
      if (c.y < m) { m = c.y; jb = j + 1; }
      if (c.z < m) { m = c.z; jb = j + 2; }
      if (c.w < m) { m = c.w; jb = j + 3; }
    }
    unsigned om = __reduce_min_sync(0xffffffffu, f2ord(m));
    float gm = ord2f(om);
    unsigned jc = (m == gm) ? (unsigned)jb : 0xffffffffu;
    unsigned jm = __reduce_min_sync(0xffffffffu, jc);
    if (lane == 0)
      atomicMin(&S.rkey[r], ((unsigned long long)om << 32) | (unsigned long long)jm);
  }
  __syncthreads();

  // ---- Phase B1: greedy init, parallel (atomicMin = first-row-wins) ----
  if (tid < 32) {
    bool has = tid < NT;
    int rarg = 0;
    if (has) {
      unsigned long long key = S.rkey[tid];
      rarg = (int)(key & 0xffffffffu);
      S.u[tid + 1] = ord2f((unsigned)(key >> 32));
      atomicMin(&S.p[rarg + 1], tid + 1);
    }
    if (tid == 0) S.u[0] = 0.0f;
    __syncwarp();
    bool lost = has && (S.p[rarg + 1] != tid + 1);
    unsigned mask = __ballot_sync(0xffffffffu, lost);
    if (lost) S.pend[__popc(mask & ((1u << tid) - 1u))] = tid + 1;  // ascending rows
    if (tid == 0) S.npend = __popc(mask);
  }
  __syncthreads();
  for (int j = tid; j <= MQ; j += THREADS)
    if (S.p[j] == PFREE) S.p[j] = 0;
  __syncthreads();

  // ---- Phase B2: Dijkstra for contested rows (warp 0, deferred duals, v0=0) ----
  if (tid < 32) {
    float v_r[32];
    #pragma unroll
    for (int k = 0; k < 32; k++) v_r[k] = 0.0f;
    const int np = S.npend;

    for (int pi = 0; pi < np; pi++) {
      const int i = S.pend[pi];
      float minv_r[32];
      #pragma unroll
      for (int k = 0; k < 32; k++) minv_r[k] = INFF;
      unsigned usedmask = 0u;
      float D = 0.0f;
      int j0 = 0;

      while (true) {
        if (j0 > 0 && ((j0 - 1) & 31) == lane) usedmask |= 1u << ((j0 - 1) >> 5);

        const int   i0  = (j0 == 0) ? i : S.p[j0];
        const float u0p = S.u[i0] - D;
        const float* crow = &S.cost[i0 - 1][0];

        float m0 = INFF, m1 = INFF, m2 = INFF, m3 = INFF;
        #pragma unroll
        for (int k = 0; k < 32; k++) {
          int   j    = lane + 1 + (k << 5);
          bool  used = (usedmask >> k) & 1u;
          float cur  = (crow[j - 1] - u0p) - v_r[k];   // absolute-distance frame
          cur = used ? INFF : cur;
          if (cur < minv_r[k]) { S.way[j] = j0; minv_r[k] = cur; }
          float mv = used ? INFF : minv_r[k];
          if ((k & 3) == 0) m0 = fminf(m0, mv);
          else if ((k & 3) == 1) m1 = fminf(m1, mv);
          else if ((k & 3) == 2) m2 = fminf(m2, mv);
          else m3 = fminf(m3, mv);
        }
        float m = fminf(fminf(m0, m1), fminf(m2, m3));

        unsigned om = __reduce_min_sync(0xffffffffu, f2ord(m));
        float gm = ord2f(om);
        unsigned msk = 0u;
        #pragma unroll
        for (int k = 0; k < 32; k++) {
          bool  used = (usedmask >> k) & 1u;
          float mv = used ? INFF : minv_r[k];
          msk |= (mv == gm) ? (1u << k) : 0u;
        }
        unsigned jl = msk ? (unsigned)(lane + 1 + ((__ffs(msk) - 1) << 5)) : 0xffffffffu;
        unsigned jm = __reduce_min_sync(0xffffffffu, jl);
        D  = gm;
        j0 = (int)jm;
        if (S.p[j0] == 0) break;
      }

      const float Dend = D;
      __syncwarp();
      unsigned mm = usedmask;
      while (mm) {
        int k = __ffs(mm) - 1; mm &= mm - 1;
        float dv = Dend - minv_r[k];
        v_r[k] -= dv;
        int j = lane + 1 + (k << 5);
        S.u[S.p[j]] += dv;          // distinct rows per used col -> race-free
      }
      if (lane == 0) { S.u[i] += Dend; S.p[0] = i; }
      __syncwarp();
      if (lane == 0) {
        int j = j0;
        while (j != 0) { int jp = S.way[j]; S.p[j] = S.p[jp]; j = jp; }
      }
      __syncwarp();
    }
    #pragma unroll
    for (int k = 0; k < 32; k++) {
      int j = lane + 1 + (k << 5);
      int r = S.p[j];
      if (r > 0) S.match_q[r - 1] = j - 1;
    }
  }
  __syncthreads();

  // ---- Phase C: CE over matched pairs, warp-per-match, fast intrinsics ----
  if (lane == 0) { S.warp_rec[wid] = 0.0; S.warp_loc[wid] = 0.0; }
  __syncwarp();

  for (int t = wid; t < NT; t += NWARP) {
    const int q = S.match_q[t];

    // rec CE: 107 channels, 4 per lane, loaded once
    const float* rb = recb + q;
    float v4[4];
    #pragma unroll
    for (int k = 0; k < 4; k++) {
      int c = lane + (k << 5);
      v4[k] = (c < CREC) ? __ldg(rb + (size_t)c * MQ) : -INFF;
    }
    float mx = fmaxf(fmaxf(v4[0], v4[1]), fmaxf(v4[2], v4[3]));
    mx = warp_max_f(mx);
    float se = 0.f;
    #pragma unroll
    for (int k = 0; k < 4; k++) {
      int c = lane + (k << 5);
      if (c < CREC) se += __expf(v4[k] - mx);
    }
    se = warp_sum_f(se);
    float rec_term = mx + __logf(se) - __ldg(rb + (size_t)S.tgt_cls[t] * MQ);

    // loc CE: 25 channels
    const float* lb = locb + q;
    float xv  = (lane < CLOC) ? __ldg(lb + (size_t)lane * MQ) : -INFF;
    float mx2 = warp_max_f(xv);
    float se2 = warp_sum_f((lane < CLOC) ? __expf(xv - mx2) : 0.f);
    float loc_term = mx2 + __logf(se2) - __ldg(lb + (size_t)t * MQ);

    if (lane == 0) {
      S.warp_rec[wid] += (double)rec_term;
      S.warp_loc[wid] += (double)loc_term;
    }
  }
  __syncthreads();

  // ---- per-batch sums + last-block final reduction ----
  if (tid == 0) {
    double r = 0.0, l = 0.0;
    #pragma unroll
    for (int w = 0; w < NWARP; w++) { r += S.warp_rec[w]; l += S.warp_loc[w]; }
    g_sums[2 * b]     = r;
    g_sums[2 * b + 1] = l;
    __threadfence();
    unsigned old = atomicAdd(&g_count, 1u);
    S.islast = (old == BS - 1);
  }
  __syncthreads();

  if (S.islast) {
    double r = (tid < BS) ? g_sums[2 * tid]     : 0.0;
    double l = (tid < BS) ? g_sums[2 * tid + 1] : 0.0;
    #pragma unroll
    for (int o = 16; o; o >>= 1) {
      r += __shfl_xor_sync(0xffffffffu, r, o);
      l += __shfl_xor_sync(0xffffffffu, l, o);
    }
    if (lane == 0 && wid < 4) { S.red_r[wid] = r; S.red_l[wid] = l; }
    __syncthreads();
    if (tid == 0) {
      double rr = S.red_r[0] + S.red_r[1] + S.red_r[2] + S.red_r[3];
      double ll = S.red_l[0] + S.red_l[1] + S.red_l[2] + S.red_l[3];
      out[0] = (float)(rr / (double)(BS * NT));
      out[1] = (float)(ll / (double)(BS * NT));
      g_count = 0;   // reset for next replay
    }
  }
}

extern "C" void kernel_launch(void* const* d_in, const int* in_sizes, int n_in,
                              void* d_out, int out_size) {
  const float* rec = (const float*)d_in[0];
  const float* loc = (const float*)d_in[1];
  const int*   tgt = (const int*)d_in[2];
  float* out = (float*)d_out;

  const int smem = (int)sizeof(Smem);
  cudaFuncSetAttribute(rec_criterion_kernel,
                       cudaFuncAttributeMaxDynamicSharedMemorySize, smem);
  rec_criterion_kernel<<<BS, THREADS, smem>>>(rec, loc, tgt, out);
}